// round 1
// baseline (speedup 1.0000x reference)
#include <cuda_runtime.h>

#define K_DIM 1024
#define N_DIM 4096
#define M_DIM 4096

// Scratch (allocation-free): staged TT-core contractions and the dense weight.
__device__ float g_A1[8 * 8 * 8 * 8 * 16];                // [m1][n1][m2][n2][r2]  = 64K
__device__ float g_A2[8 * 8 * 8 * 8 * 4 * 8 * 16];        // [m1][n1][m2][n2][m3][n3][r3] = 2M
__device__ float g_W[(size_t)K_DIM * N_DIM];              // [k][n] = 4M (tf32-rounded)

__device__ __forceinline__ unsigned f2tf32(float f) {
    unsigned u;
    asm("cvt.rna.tf32.f32 %0, %1;" : "=r"(u) : "f"(f));
    return u;
}

// Stage 1: A1[m1,n1,m2,n2,r2] = sum_r1 c0[m1,n1,r1] * core1[r1,m2,n2,r2]
__global__ void tt_stage1(const float* __restrict__ core0, const float* __restrict__ core1) {
    int i = blockIdx.x * 256 + threadIdx.x;          // 65536 total
    int r2 = i & 15, n2 = (i >> 4) & 7, m2 = (i >> 7) & 7, n1 = (i >> 10) & 7, m1 = i >> 13;
    float s = 0.f;
#pragma unroll
    for (int r1 = 0; r1 < 16; r1++)
        s += core0[(m1 * 8 + n1) * 16 + r1] * core1[((r1 * 8 + m2) * 8 + n2) * 16 + r2];
    g_A1[i] = s;
}

// Stage 2: A2[...,m3,n3,r3] = sum_r2 A1[...,r2] * core2[r2,m3,n3,r3]
__global__ void tt_stage2(const float* __restrict__ core2) {
    int i = blockIdx.x * 256 + threadIdx.x;          // 2097152 total
    int r3 = i & 15, n3 = (i >> 4) & 7, m3 = (i >> 7) & 3, j = i >> 9;
    float s = 0.f;
#pragma unroll
    for (int r2 = 0; r2 < 16; r2++)
        s += g_A1[j * 16 + r2] * core2[((r2 * 4 + m3) * 8 + n3) * 16 + r3];
    g_A2[i] = s;
}

// Stage 3: W[k,n] = sum_r3 A2[m1,n1,m2,n2,m3,n3,r3] * c3[r3,m4,n4]   (tf32-rounded)
__global__ void tt_stage3(const float* __restrict__ core3) {
    int i = blockIdx.x * 256 + threadIdx.x;          // 4194304 total
    int n = i & 4095, k = i >> 12;
    int m1 = k >> 7, m2 = (k >> 4) & 7, m3 = (k >> 2) & 3, m4 = k & 3;
    int n1 = n >> 9, n2 = (n >> 6) & 7, n3 = (n >> 3) & 7, n4 = n & 7;
    int j = ((m1 * 8 + n1) * 8 + m2) * 8 + n2;
    const float* a2 = &g_A2[(size_t)j * 512 + (m3 * 8 + n3) * 16];
    float s = 0.f;
#pragma unroll
    for (int r3 = 0; r3 < 16; r3++)
        s += a2[r3] * core3[(r3 * 4 + m4) * 8 + n4];
    g_W[i] = __uint_as_float(f2tf32(s));
}

// GEMM: Y[4096,4096] = X[4096,1024] @ W[1024,4096] + bias, tf32 tensor cores.
#define BM 128
#define BN 128
#define BK 32
#define ASTR 36    // BK + 4 pad: fragment rows land on distinct banks
#define BSTR 136   // BN + 8 pad: 136 % 32 == 8 -> conflict-free B frag loads

__global__ __launch_bounds__(256, 2) void tt_gemm(const float* __restrict__ X,
                                                  const float* __restrict__ bias,
                                                  float* __restrict__ Y) {
    __shared__ float As[BM * ASTR];
    __shared__ float Bs[BK * BSTR];

    const int tid = threadIdx.x;
    const int lane = tid & 31, warp = tid >> 5;
    const int wm = warp >> 1, wn = warp & 1;         // 4 x 2 warp grid, warp tile 32x64
    const int g = lane >> 2, t = lane & 3;
    const int bm = blockIdx.y * BM, bn = blockIdx.x * BN;

    float acc[2][8][4];
#pragma unroll
    for (int a = 0; a < 2; a++)
#pragma unroll
        for (int b = 0; b < 8; b++)
#pragma unroll
            for (int c = 0; c < 4; c++) acc[a][b][c] = 0.f;

    for (int kt = 0; kt < K_DIM; kt += BK) {
        // Load A tile (128x32), converting to tf32-rounded fp32 bits.
#pragma unroll
        for (int i = 0; i < 4; i++) {
            int idx = tid + i * 256;
            int row = idx >> 3, c4 = (idx & 7) << 2;
            float4 v = *(const float4*)&X[(size_t)(bm + row) * K_DIM + kt + c4];
            float* p = &As[row * ASTR + c4];
            p[0] = __uint_as_float(f2tf32(v.x));
            p[1] = __uint_as_float(f2tf32(v.y));
            p[2] = __uint_as_float(f2tf32(v.z));
            p[3] = __uint_as_float(f2tf32(v.w));
        }
        // Load B tile (32x128); W is already tf32-rounded.
#pragma unroll
        for (int i = 0; i < 4; i++) {
            int idx = tid + i * 256;
            int row = idx >> 5, c4 = (idx & 31) << 2;
            float4 v = *(const float4*)&g_W[(size_t)(kt + row) * N_DIM + bn + c4];
            float* p = &Bs[row * BSTR + c4];
            p[0] = v.x; p[1] = v.y; p[2] = v.z; p[3] = v.w;
        }
        __syncthreads();

#pragma unroll
        for (int kk = 0; kk < BK; kk += 8) {
            unsigned a[2][4], b[8][2];
#pragma unroll
            for (int mt = 0; mt < 2; mt++) {
                int r0 = wm * 32 + mt * 16 + g;
                a[mt][0] = __float_as_uint(As[r0 * ASTR + kk + t]);
                a[mt][1] = __float_as_uint(As[(r0 + 8) * ASTR + kk + t]);
                a[mt][2] = __float_as_uint(As[r0 * ASTR + kk + t + 4]);
                a[mt][3] = __float_as_uint(As[(r0 + 8) * ASTR + kk + t + 4]);
            }
#pragma unroll
            for (int nt = 0; nt < 8; nt++) {
                int c0 = wn * 64 + nt * 8 + g;
                b[nt][0] = __float_as_uint(Bs[(kk + t) * BSTR + c0]);
                b[nt][1] = __float_as_uint(Bs[(kk + t + 4) * BSTR + c0]);
            }
#pragma unroll
            for (int mt = 0; mt < 2; mt++)
#pragma unroll
                for (int nt = 0; nt < 8; nt++) {
                    asm volatile(
                        "mma.sync.aligned.m16n8k8.row.col.f32.tf32.tf32.f32 "
                        "{%0,%1,%2,%3},{%4,%5,%6,%7},{%8,%9},{%0,%1,%2,%3};"
                        : "+f"(acc[mt][nt][0]), "+f"(acc[mt][nt][1]),
                          "+f"(acc[mt][nt][2]), "+f"(acc[mt][nt][3])
                        : "r"(a[mt][0]), "r"(a[mt][1]), "r"(a[mt][2]), "r"(a[mt][3]),
                          "r"(b[nt][0]), "r"(b[nt][1]));
                }
        }
        __syncthreads();
    }

    // Epilogue: bias add + store (float2: c0/c1 are adjacent columns).
#pragma unroll
    for (int mt = 0; mt < 2; mt++) {
        int row = bm + wm * 32 + mt * 16 + g;
#pragma unroll
        for (int nt = 0; nt < 8; nt++) {
            int col = bn + wn * 64 + nt * 8 + 2 * t;
            float b0 = bias[col], b1 = bias[col + 1];
            *(float2*)&Y[(size_t)row * N_DIM + col] =
                make_float2(acc[mt][nt][0] + b0, acc[mt][nt][1] + b1);
            *(float2*)&Y[(size_t)(row + 8) * N_DIM + col] =
                make_float2(acc[mt][nt][2] + b0, acc[mt][nt][3] + b1);
        }
    }
}

extern "C" void kernel_launch(void* const* d_in, const int* in_sizes, int n_in,
                              void* d_out, int out_size) {
    const float* x     = (const float*)d_in[0];
    const float* core0 = (const float*)d_in[1];
    const float* core1 = (const float*)d_in[2];
    const float* core2 = (const float*)d_in[3];
    const float* core3 = (const float*)d_in[4];
    const float* bias  = (const float*)d_in[5];
    float* y = (float*)d_out;

    tt_stage1<<<256, 256>>>(core0, core1);
    tt_stage2<<<8192, 256>>>(core2);
    tt_stage3<<<16384, 256>>>(core3);

    dim3 grid(N_DIM / BN, M_DIM / BM);   // 32 x 32
    tt_gemm<<<grid, 256>>>(x, bias, y);
}

// round 4
// speedup vs baseline: 1.0225x; 1.0225x over previous
#include <cuda_runtime.h>
#include <cstdint>

#define K_DIM 1024
#define N_DIM 4096
#define M_DIM 4096

// Scratch (allocation-free): staged TT-core contractions, dense weight, rounded X.
__device__ float g_A1[65536];                       // [m1][n1][m2][n2][r2]
__device__ float g_A2[2097152];                     // [m1][n1][m2][n2][m3][n3][r3]
__device__ float g_Wt[(size_t)N_DIM * K_DIM];       // TRANSPOSED: [n][k], tf32-rounded
__device__ float g_Xr[(size_t)M_DIM * K_DIM];       // X, tf32-rounded

__device__ __forceinline__ unsigned f2tf32(float f) {
    unsigned u;
    asm("cvt.rna.tf32.f32 %0, %1;" : "=r"(u) : "f"(f));
    return u;
}
__device__ __forceinline__ uint32_t smem_u32(const void* p) {
    uint32_t a;
    asm("{ .reg .u64 t; cvta.to.shared.u64 t, %1; cvt.u32.u64 %0, t; }" : "=r"(a) : "l"(p));
    return a;
}

// ---------------- TT-core staging ----------------

__global__ void tt_stage1(const float* __restrict__ core0, const float* __restrict__ core1) {
    int i = blockIdx.x * 256 + threadIdx.x;          // 65536
    int r2 = i & 15, n2 = (i >> 4) & 7, m2 = (i >> 7) & 7, n1 = (i >> 10) & 7, m1 = i >> 13;
    float s = 0.f;
#pragma unroll
    for (int r1 = 0; r1 < 16; r1++)
        s += core0[(m1 * 8 + n1) * 16 + r1] * core1[((r1 * 8 + m2) * 8 + n2) * 16 + r2];
    g_A1[i] = s;
}

__global__ void tt_stage2(const float* __restrict__ core2) {
    int i = blockIdx.x * 256 + threadIdx.x;          // 2097152
    int r3 = i & 15, n3 = (i >> 4) & 7, m3 = (i >> 7) & 3, j = i >> 9;
    float s = 0.f;
#pragma unroll
    for (int r2 = 0; r2 < 16; r2++)
        s += g_A1[j * 16 + r2] * core2[((r2 * 4 + m3) * 8 + n3) * 16 + r3];
    g_A2[i] = s;
}

// Wt[n][k] = sum_r3 A2[m1,n1,m2,n2,m3,n3,r3] * c3[r3,m4,n4]; 4 k-values (m4) per thread.
__global__ void tt_stage3(const float* __restrict__ core3) {
    int i = blockIdx.x * 256 + threadIdx.x;          // 1048576
    int khi = i & 255;                                // m1(3) m2(3) m3(2)
    int n = i >> 8;
    int m1 = khi >> 5, m2 = (khi >> 2) & 7, m3 = khi & 3;
    int n1 = n >> 9, n2 = (n >> 6) & 7, n3 = (n >> 3) & 7, n4 = n & 7;
    const float* a2 = &g_A2[(size_t)(((m1 * 8 + n1) * 8 + m2) * 8 + n2) * 512 + (m3 * 8 + n3) * 16];
    float s0 = 0.f, s1 = 0.f, s2 = 0.f, s3 = 0.f;
#pragma unroll
    for (int r3 = 0; r3 < 16; r3++) {
        float a = a2[r3];
        s0 += a * core3[(r3 * 4 + 0) * 8 + n4];
        s1 += a * core3[(r3 * 4 + 1) * 8 + n4];
        s2 += a * core3[(r3 * 4 + 2) * 8 + n4];
        s3 += a * core3[(r3 * 4 + 3) * 8 + n4];
    }
    float4 o;
    o.x = __uint_as_float(f2tf32(s0));
    o.y = __uint_as_float(f2tf32(s1));
    o.z = __uint_as_float(f2tf32(s2));
    o.w = __uint_as_float(f2tf32(s3));
    *(float4*)&g_Wt[(size_t)n * K_DIM + khi * 4] = o;
}

// Pre-round X to tf32 so the GEMM inner loop has zero conversion work.
__global__ void x_round(const float* __restrict__ X) {
    int i = blockIdx.x * 256 + threadIdx.x;          // 1048576 float4s
    float4 v = ((const float4*)X)[i];
    float4 o;
    o.x = __uint_as_float(f2tf32(v.x));
    o.y = __uint_as_float(f2tf32(v.y));
    o.z = __uint_as_float(f2tf32(v.z));
    o.w = __uint_as_float(f2tf32(v.w));
    ((float4*)g_Xr)[i] = o;
}

// ---------------- tf32 mma.sync GEMM, cp.async 3-stage pipeline ----------------
// CTA 128x128, 128 threads (4 warps, 2x2 grid), warp tile 64x64, BK=32.
// Smem layout per operand: 128 rows x 128B, 16B units XOR-swizzled by (row&7).

#define BK 32
#define STAGE_BYTES 32768            // A 16KB + B 16KB
#define NSTAGE 3
#define SMEM_SZ (NSTAGE * STAGE_BYTES)
#define NITER (K_DIM / BK)

__device__ __forceinline__ void cp16(uint32_t dst, const float* src) {
    asm volatile("cp.async.cg.shared.global [%0], [%1], 16;" :: "r"(dst), "l"(src) : "memory");
}

__global__ __launch_bounds__(128, 2) void tt_gemm2(const float* __restrict__ bias,
                                                   float* __restrict__ Y) {
    extern __shared__ __align__(1024) char smem[];
    const uint32_t sb = smem_u32(smem);
    const int tid = threadIdx.x, lane = tid & 31, warp = tid >> 5;
    const int wm = warp >> 1, wn = warp & 1;
    const int g = lane >> 2, t = lane & 3;
    const int bm = blockIdx.y * 128, bn = blockIdx.x * 128;

    const float* gA = g_Xr + (size_t)bm * K_DIM;
    const float* gB = g_Wt + (size_t)bn * K_DIM;

    float acc[4][8][4];
#pragma unroll
    for (int a = 0; a < 4; a++)
#pragma unroll
        for (int b = 0; b < 8; b++)
#pragma unroll
            for (int c = 0; c < 4; c++) acc[a][b][c] = 0.f;

    // Per-thread fixed chunk coords: chunk c = i*128 + tid -> row m = c>>3, 16B col j = c&7.
    // 8-thread phases share one row, cover 8 distinct swizzled cols: conflict-free.
    auto issue = [&](int it) {
        if (it < NITER) {
            const int s = it % NSTAGE;
            const uint32_t a0 = sb + s * STAGE_BYTES;
            const uint32_t b0 = a0 + 16384;
            const int kt = it * BK;
#pragma unroll
            for (int i = 0; i < 8; i++) {
                int c = i * 128 + tid;
                int m = c >> 3, j = c & 7;
                uint32_t off = (uint32_t)(m * 128 + ((j ^ (m & 7)) << 4));
                cp16(a0 + off, gA + (size_t)m * K_DIM + kt + j * 4);
                cp16(b0 + off, gB + (size_t)m * K_DIM + kt + j * 4);
            }
        }
        asm volatile("cp.async.commit_group;" ::: "memory");
    };

    issue(0); issue(1); issue(2);

    int rowA[4], rowB[8];
#pragma unroll
    for (int mt = 0; mt < 4; mt++) rowA[mt] = (wm * 64 + mt * 16 + g) * 128;
#pragma unroll
    for (int nt = 0; nt < 8; nt++) rowB[nt] = (wn * 64 + nt * 8 + g) * 128;

    for (int it = 0; it < NITER; it++) {
        const int s = it % NSTAGE;
        asm volatile("cp.async.wait_group 2;" ::: "memory");
        __syncthreads();
        const uint32_t a0 = sb + s * STAGE_BYTES;
        const uint32_t b0 = a0 + 16384;

#pragma unroll
        for (int kk = 0; kk < 4; kk++) {                 // K sub-step of 8
            const int u0 = kk * 2;
            const uint32_t o0 = (uint32_t)((((u0)     ^ g) << 4) + t * 4);
            const uint32_t o1 = (uint32_t)((((u0 + 1) ^ g) << 4) + t * 4);
            unsigned a[4][4], b[8][2];
#pragma unroll
            for (int mt = 0; mt < 4; mt++) {
                uint32_t r0 = a0 + rowA[mt];
                asm("ld.shared.b32 %0,[%1];" : "=r"(a[mt][0]) : "r"(r0 + o0));
                asm("ld.shared.b32 %0,[%1];" : "=r"(a[mt][1]) : "r"(r0 + 1024 + o0));
                asm("ld.shared.b32 %0,[%1];" : "=r"(a[mt][2]) : "r"(r0 + o1));
                asm("ld.shared.b32 %0,[%1];" : "=r"(a[mt][3]) : "r"(r0 + 1024 + o1));
            }
#pragma unroll
            for (int nt = 0; nt < 8; nt++) {
                uint32_t r0 = b0 + rowB[nt];
                asm("ld.shared.b32 %0,[%1];" : "=r"(b[nt][0]) : "r"(r0 + o0));
                asm("ld.shared.b32 %0,[%1];" : "=r"(b[nt][1]) : "r"(r0 + o1));
            }
#pragma unroll
            for (int mt = 0; mt < 4; mt++)
#pragma unroll
                for (int nt = 0; nt < 8; nt++) {
                    asm volatile(
                        "mma.sync.aligned.m16n8k8.row.col.f32.tf32.tf32.f32 "
                        "{%0,%1,%2,%3},{%4,%5,%6,%7},{%8,%9},{%0,%1,%2,%3};"
                        : "+f"(acc[mt][nt][0]), "+f"(acc[mt][nt][1]),
                          "+f"(acc[mt][nt][2]), "+f"(acc[mt][nt][3])
                        : "r"(a[mt][0]), "r"(a[mt][1]), "r"(a[mt][2]), "r"(a[mt][3]),
                          "r"(b[nt][0]), "r"(b[nt][1]));
                }
        }
        __syncthreads();
        issue(it + 3);
    }

    // Epilogue: bias add + float2 stores (full 32B sectors per 8-lane group).
#pragma unroll
    for (int mt = 0; mt < 4; mt++) {
        size_t r0 = (size_t)(bm + wm * 64 + mt * 16 + g);
#pragma unroll
        for (int nt = 0; nt < 8; nt++) {
            int col = bn + wn * 64 + nt * 8 + 2 * t;
            float b0v = bias[col], b1v = bias[col + 1];
            *(float2*)&Y[r0 * N_DIM + col] =
                make_float2(acc[mt][nt][0] + b0v, acc[mt][nt][1] + b1v);
            *(float2*)&Y[(r0 + 8) * N_DIM + col] =
                make_float2(acc[mt][nt][2] + b0v, acc[mt][nt][3] + b1v);
        }
    }
}

extern "C" void kernel_launch(void* const* d_in, const int* in_sizes, int n_in,
                              void* d_out, int out_size) {
    const float* x     = (const float*)d_in[0];
    const float* core0 = (const float*)d_in[1];
    const float* core1 = (const float*)d_in[2];
    const float* core2 = (const float*)d_in[3];
    const float* core3 = (const float*)d_in[4];
    const float* bias  = (const float*)d_in[5];
    float* y = (float*)d_out;

    cudaFuncSetAttribute(tt_gemm2, cudaFuncAttributeMaxDynamicSharedMemorySize, SMEM_SZ);

    x_round<<<4096, 256>>>(x);
    tt_stage1<<<256, 256>>>(core0, core1);
    tt_stage2<<<8192, 256>>>(core2);
    tt_stage3<<<4096, 256>>>(core3);

    dim3 grid(N_DIM / 128, M_DIM / 128);   // 32 x 32
    tt_gemm2<<<grid, 128, SMEM_SZ>>>(bias, y);
}

// round 5
// speedup vs baseline: 1.1712x; 1.1454x over previous
#include <cuda_runtime.h>
#include <cstdint>

#define K_DIM 1024
#define N_DIM 4096
#define M_DIM 4096

// Scratch (allocation-free).
__device__ float g_A1[65536];                       // [m1][n1][m2][n2][r2]
__device__ float g_Wt[(size_t)N_DIM * K_DIM];       // TRANSPOSED: [n][k], tf32-rounded
__device__ float g_Xr[(size_t)M_DIM * K_DIM];       // X, tf32-rounded

__device__ __forceinline__ unsigned f2tf32(float f) {
    unsigned u;
    asm("cvt.rna.tf32.f32 %0, %1;" : "=r"(u) : "f"(f));
    return u;
}
__device__ __forceinline__ uint32_t smem_u32(const void* p) {
    uint32_t a;
    asm("{ .reg .u64 t; cvta.to.shared.u64 t, %1; cvt.u32.u64 %0, t; }" : "=r"(a) : "l"(p));
    return a;
}

// ---------------- TT-core staging ----------------

__global__ void tt_stage1(const float* __restrict__ core0, const float* __restrict__ core1) {
    int i = blockIdx.x * 256 + threadIdx.x;          // 65536
    int r2 = i & 15, n2 = (i >> 4) & 7, m2 = (i >> 7) & 7, n1 = (i >> 10) & 7, m1 = i >> 13;
    float s = 0.f;
#pragma unroll
    for (int r1 = 0; r1 < 16; r1++)
        s += core0[(m1 * 8 + n1) * 16 + r1] * core1[((r1 * 8 + m2) * 8 + n2) * 16 + r2];
    g_A1[i] = s;
}

// Fused stage2+stage3: one block per (n1,n2,n3). Thread owns (m1,m2,m3); t[r3] in regs.
// Wt[n][k] = sum_{r2,r3} A1[m1,n1,m2,n2,r2] * core2[r2,m3,n3,r3] * core3[r3,m4,n4]
__global__ __launch_bounds__(256) void tt_stage23(const float* __restrict__ core2,
                                                  const float* __restrict__ core3) {
    __shared__ float sA1[1024];   // [m1][m2][r2]
    __shared__ float sC2[1024];   // [r2][m3][r3]
    __shared__ float sC3[512];    // [r3][m4][n4]

    const int b = blockIdx.x;                         // 512 = (n1,n2,n3)
    const int n1 = b >> 6, n2 = (b >> 3) & 7, n3 = b & 7;
    const int tid = threadIdx.x;

    {   // sA1: c = m1*32 + m2*4 + r2q  ->  float4
        int m1 = tid >> 5, m2 = (tid >> 2) & 7, r2q = tid & 3;
        ((float4*)sA1)[tid] = *(const float4*)&g_A1[m1 * 8192 + n1 * 1024 + m2 * 128 + n2 * 16 + r2q * 4];
    }
    {   // sC2: c = r2*16 + m3*4 + r3q
        int r2 = tid >> 4, m3 = (tid >> 2) & 3, r3q = tid & 3;
        ((float4*)sC2)[tid] = *(const float4*)&core2[r2 * 512 + m3 * 128 + n3 * 16 + r3q * 4];
    }
    if (tid < 128) ((float4*)sC3)[tid] = ((const float4*)core3)[tid];
    __syncthreads();

    const int m1 = tid >> 5, m2 = (tid >> 2) & 7, m3 = tid & 3;
    float a[16], t[16];
#pragma unroll
    for (int r2 = 0; r2 < 16; r2++) a[r2] = sA1[m1 * 128 + m2 * 16 + r2];
#pragma unroll
    for (int r3 = 0; r3 < 16; r3++) t[r3] = 0.f;
#pragma unroll
    for (int r2 = 0; r2 < 16; r2++) {
        float av = a[r2];
#pragma unroll
        for (int r3 = 0; r3 < 16; r3++) t[r3] += av * sC2[r2 * 64 + m3 * 16 + r3];
    }

    // k4 chunk = m1*32 + m2*4 + m3 == tid  ->  coalesced float4 rows of g_Wt.
    const size_t nbase = (size_t)b * 8;
#pragma unroll
    for (int n4 = 0; n4 < 8; n4++) {
        float s[4];
#pragma unroll
        for (int m4 = 0; m4 < 4; m4++) {
            float acc = 0.f;
#pragma unroll
            for (int r3 = 0; r3 < 16; r3++) acc += t[r3] * sC3[r3 * 32 + m4 * 8 + n4];
            s[m4] = acc;
        }
        float4 o;
        o.x = __uint_as_float(f2tf32(s[0]));
        o.y = __uint_as_float(f2tf32(s[1]));
        o.z = __uint_as_float(f2tf32(s[2]));
        o.w = __uint_as_float(f2tf32(s[3]));
        *(float4*)&g_Wt[(nbase + n4) * K_DIM + tid * 4] = o;
    }
}

// Pre-round X to tf32 so the GEMM inner loop has zero conversion work.
__global__ void x_round(const float* __restrict__ X) {
    int i = blockIdx.x * 256 + threadIdx.x;          // 1048576 float4s
    float4 v = ((const float4*)X)[i];
    float4 o;
    o.x = __uint_as_float(f2tf32(v.x));
    o.y = __uint_as_float(f2tf32(v.y));
    o.z = __uint_as_float(f2tf32(v.z));
    o.w = __uint_as_float(f2tf32(v.w));
    ((float4*)g_Xr)[i] = o;
}

// ---------------- tf32 mma.sync GEMM, cp.async 3-stage pipeline ----------------
// CTA 128x256, 256 threads (8 warps, 2x4), warp tile 64x64, BK=32.
// Smem rows of 128B, 16B units XOR-swizzled by (row&7).

#define BK 32
#define A_BYTES 16384                // 128 rows x 128B
#define B_BYTES 32768                // 256 rows x 128B
#define STAGE_BYTES (A_BYTES + B_BYTES)
#define NSTAGE 3
#define SMEM_SZ (NSTAGE * STAGE_BYTES)
#define NITER (K_DIM / BK)

__device__ __forceinline__ void cp16(uint32_t dst, const float* src) {
    asm volatile("cp.async.cg.shared.global [%0], [%1], 16;" :: "r"(dst), "l"(src) : "memory");
}

__global__ __launch_bounds__(256, 1) void tt_gemm2(const float* __restrict__ bias,
                                                   float* __restrict__ Y) {
    extern __shared__ __align__(1024) char smem[];
    const uint32_t sb = smem_u32(smem);
    const int tid = threadIdx.x, lane = tid & 31, warp = tid >> 5;
    const int wm = warp >> 2, wn = warp & 3;
    const int g = lane >> 2, t = lane & 3;
    const int bm = blockIdx.y * 128, bn = blockIdx.x * 256;

    const float* gA = g_Xr + (size_t)bm * K_DIM;
    const float* gB = g_Wt + (size_t)bn * K_DIM;

    float acc[4][8][4];
#pragma unroll
    for (int a = 0; a < 4; a++)
#pragma unroll
        for (int b = 0; b < 8; b++)
#pragma unroll
            for (int c = 0; c < 4; c++) acc[a][b][c] = 0.f;

    auto issue = [&](int it) {
        if (it < NITER) {
            const int s = it % NSTAGE;
            const uint32_t a0 = sb + s * STAGE_BYTES;
            const uint32_t b0 = a0 + A_BYTES;
            const int kt = it * BK;
#pragma unroll
            for (int i = 0; i < 4; i++) {            // A: 1024 chunks
                int c = i * 256 + tid;
                int m = c >> 3, j = c & 7;
                uint32_t off = (uint32_t)(m * 128 + ((j ^ (m & 7)) << 4));
                cp16(a0 + off, gA + (size_t)m * K_DIM + kt + j * 4);
            }
#pragma unroll
            for (int i = 0; i < 8; i++) {            // B: 2048 chunks
                int c = i * 256 + tid;
                int m = c >> 3, j = c & 7;
                uint32_t off = (uint32_t)(m * 128 + ((j ^ (m & 7)) << 4));
                cp16(b0 + off, gB + (size_t)m * K_DIM + kt + j * 4);
            }
        }
        asm volatile("cp.async.commit_group;" ::: "memory");
    };

    issue(0); issue(1); issue(2);

    int rowA[4], rowB[8];
#pragma unroll
    for (int mt = 0; mt < 4; mt++) rowA[mt] = (wm * 64 + mt * 16 + g) * 128;
#pragma unroll
    for (int nt = 0; nt < 8; nt++) rowB[nt] = (wn * 64 + nt * 8 + g) * 128;

    for (int it = 0; it < NITER; it++) {
        const int s = it % NSTAGE;
        asm volatile("cp.async.wait_group 2;" ::: "memory");
        __syncthreads();
        const uint32_t a0 = sb + s * STAGE_BYTES;
        const uint32_t b0 = a0 + A_BYTES;

#pragma unroll
        for (int kk = 0; kk < 4; kk++) {             // K sub-step of 8
            const int u0 = kk * 2;
            const uint32_t o0 = (uint32_t)((((u0)     ^ g) << 4) + t * 4);
            const uint32_t o1 = (uint32_t)((((u0 + 1) ^ g) << 4) + t * 4);
            unsigned a[4][4], b[8][2];
#pragma unroll
            for (int mt = 0; mt < 4; mt++) {
                uint32_t r0 = a0 + rowA[mt];
                asm("ld.shared.b32 %0,[%1];" : "=r"(a[mt][0]) : "r"(r0 + o0));
                asm("ld.shared.b32 %0,[%1];" : "=r"(a[mt][1]) : "r"(r0 + 1024 + o0));
                asm("ld.shared.b32 %0,[%1];" : "=r"(a[mt][2]) : "r"(r0 + o1));
                asm("ld.shared.b32 %0,[%1];" : "=r"(a[mt][3]) : "r"(r0 + 1024 + o1));
            }
#pragma unroll
            for (int nt = 0; nt < 8; nt++) {
                uint32_t r0 = b0 + rowB[nt];
                asm("ld.shared.b32 %0,[%1];" : "=r"(b[nt][0]) : "r"(r0 + o0));
                asm("ld.shared.b32 %0,[%1];" : "=r"(b[nt][1]) : "r"(r0 + o1));
            }
#pragma unroll
            for (int mt = 0; mt < 4; mt++)
#pragma unroll
                for (int nt = 0; nt < 8; nt++) {
                    asm volatile(
                        "mma.sync.aligned.m16n8k8.row.col.f32.tf32.tf32.f32 "
                        "{%0,%1,%2,%3},{%4,%5,%6,%7},{%8,%9},{%0,%1,%2,%3};"
                        : "+f"(acc[mt][nt][0]), "+f"(acc[mt][nt][1]),
                          "+f"(acc[mt][nt][2]), "+f"(acc[mt][nt][3])
                        : "r"(a[mt][0]), "r"(a[mt][1]), "r"(a[mt][2]), "r"(a[mt][3]),
                          "r"(b[nt][0]), "r"(b[nt][1]));
                }
        }
        __syncthreads();
        issue(it + 3);
    }

    // Epilogue: bias add + float2 stores.
#pragma unroll
    for (int mt = 0; mt < 4; mt++) {
        size_t r0 = (size_t)(bm + wm * 64 + mt * 16 + g);
#pragma unroll
        for (int nt = 0; nt < 8; nt++) {
            int col = bn + wn * 64 + nt * 8 + 2 * t;
            float b0v = bias[col], b1v = bias[col + 1];
            *(float2*)&Y[r0 * N_DIM + col] =
                make_float2(acc[mt][nt][0] + b0v, acc[mt][nt][1] + b1v);
            *(float2*)&Y[(r0 + 8) * N_DIM + col] =
                make_float2(acc[mt][nt][2] + b0v, acc[mt][nt][3] + b1v);
        }
    }
}

extern "C" void kernel_launch(void* const* d_in, const int* in_sizes, int n_in,
                              void* d_out, int out_size) {
    const float* x     = (const float*)d_in[0];
    const float* core0 = (const float*)d_in[1];
    const float* core1 = (const float*)d_in[2];
    const float* core2 = (const float*)d_in[3];
    const float* core3 = (const float*)d_in[4];
    const float* bias  = (const float*)d_in[5];
    float* y = (float*)d_out;

    cudaFuncSetAttribute(tt_gemm2, cudaFuncAttributeMaxDynamicSharedMemorySize, SMEM_SZ);

    x_round<<<4096, 256>>>(x);
    tt_stage1<<<256, 256>>>(core0, core1);
    tt_stage23<<<512, 256>>>(core2, core3);

    dim3 grid(N_DIM / 256, M_DIM / 128);   // 16 x 32
    tt_gemm2<<<grid, 256, SMEM_SZ>>>(bias, y);
}

// round 6
// speedup vs baseline: 1.3555x; 1.1573x over previous
#include <cuda_runtime.h>
#include <cstdint>

#define K_DIM 1024
#define N_DIM 4096
#define M_DIM 4096

// Scratch (allocation-free).
__device__ float g_A1[65536];                       // [m1][n1][m2][n2][r2]
__device__ float g_Wt[(size_t)N_DIM * K_DIM];       // TRANSPOSED: [n][k], tf32-rounded
__device__ float g_Xr[(size_t)M_DIM * K_DIM];       // X, tf32-rounded

__device__ __forceinline__ unsigned f2tf32(float f) {
    unsigned u;
    asm("cvt.rna.tf32.f32 %0, %1;" : "=r"(u) : "f"(f));
    return u;
}
__device__ __forceinline__ uint32_t smem_u32(const void* p) {
    uint32_t a;
    asm("{ .reg .u64 t; cvta.to.shared.u64 t, %1; cvt.u32.u64 %0, t; }" : "=r"(a) : "l"(p));
    return a;
}

// ---------------- TT-core staging ----------------

__global__ void tt_stage1(const float* __restrict__ core0, const float* __restrict__ core1) {
    int i = blockIdx.x * 256 + threadIdx.x;          // 65536
    int r2 = i & 15, n2 = (i >> 4) & 7, m2 = (i >> 7) & 7, n1 = (i >> 10) & 7, m1 = i >> 13;
    float s = 0.f;
#pragma unroll
    for (int r1 = 0; r1 < 16; r1++)
        s += core0[(m1 * 8 + n1) * 16 + r1] * core1[((r1 * 8 + m2) * 8 + n2) * 16 + r2];
    g_A1[i] = s;
}

// Fused stage2+stage3: one block per (n1,n2,n3). Thread owns (m1,m2,m3); t[r3] in regs.
__global__ __launch_bounds__(256) void tt_stage23(const float* __restrict__ core2,
                                                  const float* __restrict__ core3) {
    __shared__ float sA1[1024];   // [m1][m2][r2]
    __shared__ float sC2[1024];   // [r2][m3][r3]
    __shared__ float sC3[512];    // [r3][m4][n4]

    const int b = blockIdx.x;                         // 512 = (n1,n2,n3)
    const int n1 = b >> 6, n2 = (b >> 3) & 7, n3 = b & 7;
    const int tid = threadIdx.x;

    {
        int m1 = tid >> 5, m2 = (tid >> 2) & 7, r2q = tid & 3;
        ((float4*)sA1)[tid] = *(const float4*)&g_A1[m1 * 8192 + n1 * 1024 + m2 * 128 + n2 * 16 + r2q * 4];
    }
    {
        int r2 = tid >> 4, m3 = (tid >> 2) & 3, r3q = tid & 3;
        ((float4*)sC2)[tid] = *(const float4*)&core2[r2 * 512 + m3 * 128 + n3 * 16 + r3q * 4];
    }
    if (tid < 128) ((float4*)sC3)[tid] = ((const float4*)core3)[tid];
    __syncthreads();

    const int m1 = tid >> 5, m2 = (tid >> 2) & 7, m3 = tid & 3;
    float a[16], t[16];
#pragma unroll
    for (int r2 = 0; r2 < 16; r2++) a[r2] = sA1[m1 * 128 + m2 * 16 + r2];
#pragma unroll
    for (int r3 = 0; r3 < 16; r3++) t[r3] = 0.f;
#pragma unroll
    for (int r2 = 0; r2 < 16; r2++) {
        float av = a[r2];
#pragma unroll
        for (int r3 = 0; r3 < 16; r3++) t[r3] += av * sC2[r2 * 64 + m3 * 16 + r3];
    }

    const size_t nbase = (size_t)b * 8;
#pragma unroll
    for (int n4 = 0; n4 < 8; n4++) {
        float s[4];
#pragma unroll
        for (int m4 = 0; m4 < 4; m4++) {
            float acc = 0.f;
#pragma unroll
            for (int r3 = 0; r3 < 16; r3++) acc += t[r3] * sC3[r3 * 32 + m4 * 8 + n4];
            s[m4] = acc;
        }
        float4 o;
        o.x = __uint_as_float(f2tf32(s[0]));
        o.y = __uint_as_float(f2tf32(s[1]));
        o.z = __uint_as_float(f2tf32(s[2]));
        o.w = __uint_as_float(f2tf32(s[3]));
        *(float4*)&g_Wt[(nbase + n4) * K_DIM + tid * 4] = o;
    }
}

// Pre-round X to tf32 so the GEMM inner loop has zero conversion work.
__global__ void x_round(const float* __restrict__ X) {
    int i = blockIdx.x * 256 + threadIdx.x;          // 1048576 float4s
    float4 v = ((const float4*)X)[i];
    float4 o;
    o.x = __uint_as_float(f2tf32(v.x));
    o.y = __uint_as_float(f2tf32(v.y));
    o.z = __uint_as_float(f2tf32(v.z));
    o.w = __uint_as_float(f2tf32(v.w));
    ((float4*)g_Xr)[i] = o;
}

// ---------------- tf32 mma.sync GEMM, cp.async 3-stage pipeline ----------------
// CTA 128x128, 128 threads (4 warps, 2x2 grid), warp tile 64x64, BK=32.
// 96KB smem -> 2 CTAs/SM so barrier/issue phases of one CTA overlap MMAs of the other.
// Smem rows of 128B, 16B units XOR-swizzled by (row&7).

#define BK 32
#define STAGE_BYTES 32768            // A 16KB + B 16KB
#define NSTAGE 3
#define SMEM_SZ (NSTAGE * STAGE_BYTES)
#define NITER (K_DIM / BK)

__device__ __forceinline__ void cp16(uint32_t dst, const float* src) {
    asm volatile("cp.async.cg.shared.global [%0], [%1], 16;" :: "r"(dst), "l"(src) : "memory");
}

__global__ __launch_bounds__(128, 2) void tt_gemm2(const float* __restrict__ bias,
                                                   float* __restrict__ Y) {
    extern __shared__ __align__(1024) char smem[];
    const uint32_t sb = smem_u32(smem);
    const int tid = threadIdx.x, lane = tid & 31, warp = tid >> 5;
    const int wm = warp >> 1, wn = warp & 1;
    const int g = lane >> 2, t = lane & 3;
    const int bm = blockIdx.y * 128, bn = blockIdx.x * 128;

    const float* gA = g_Xr + (size_t)bm * K_DIM;
    const float* gB = g_Wt + (size_t)bn * K_DIM;

    float acc[4][8][4];
#pragma unroll
    for (int a = 0; a < 4; a++)
#pragma unroll
        for (int b = 0; b < 8; b++)
#pragma unroll
            for (int c = 0; c < 4; c++) acc[a][b][c] = 0.f;

    // chunk c = i*128 + tid -> row m = c>>3, 16B col j = c&7; conflict-free in 8-thread phases.
    auto issue = [&](int it) {
        if (it < NITER) {
            const int s = it % NSTAGE;
            const uint32_t a0 = sb + s * STAGE_BYTES;
            const uint32_t b0 = a0 + 16384;
            const int kt = it * BK;
#pragma unroll
            for (int i = 0; i < 8; i++) {
                int c = i * 128 + tid;
                int m = c >> 3, j = c & 7;
                uint32_t off = (uint32_t)(m * 128 + ((j ^ (m & 7)) << 4));
                cp16(a0 + off, gA + (size_t)m * K_DIM + kt + j * 4);
                cp16(b0 + off, gB + (size_t)m * K_DIM + kt + j * 4);
            }
        }
        asm volatile("cp.async.commit_group;" ::: "memory");
    };

    issue(0); issue(1); issue(2);

    int rowA[4], rowB[8];
#pragma unroll
    for (int mt = 0; mt < 4; mt++) rowA[mt] = (wm * 64 + mt * 16 + g) * 128;
#pragma unroll
    for (int nt = 0; nt < 8; nt++) rowB[nt] = (wn * 64 + nt * 8 + g) * 128;

    for (int it = 0; it < NITER; it++) {
        const int s = it % NSTAGE;
        asm volatile("cp.async.wait_group 2;" ::: "memory");
        __syncthreads();
        const uint32_t a0 = sb + s * STAGE_BYTES;
        const uint32_t b0 = a0 + 16384;

#pragma unroll
        for (int kk = 0; kk < 4; kk++) {             // K sub-step of 8
            const int u0 = kk * 2;
            const uint32_t o0 = (uint32_t)((((u0)     ^ g) << 4) + t * 4);
            const uint32_t o1 = (uint32_t)((((u0 + 1) ^ g) << 4) + t * 4);
            unsigned a[4][4], b[8][2];
#pragma unroll
            for (int mt = 0; mt < 4; mt++) {
                uint32_t r0 = a0 + rowA[mt];
                asm("ld.shared.b32 %0,[%1];" : "=r"(a[mt][0]) : "r"(r0 + o0));
                asm("ld.shared.b32 %0,[%1];" : "=r"(a[mt][1]) : "r"(r0 + 1024 + o0));
                asm("ld.shared.b32 %0,[%1];" : "=r"(a[mt][2]) : "r"(r0 + o1));
                asm("ld.shared.b32 %0,[%1];" : "=r"(a[mt][3]) : "r"(r0 + 1024 + o1));
            }
#pragma unroll
            for (int nt = 0; nt < 8; nt++) {
                uint32_t r0 = b0 + rowB[nt];
                asm("ld.shared.b32 %0,[%1];" : "=r"(b[nt][0]) : "r"(r0 + o0));
                asm("ld.shared.b32 %0,[%1];" : "=r"(b[nt][1]) : "r"(r0 + o1));
            }
#pragma unroll
            for (int mt = 0; mt < 4; mt++)
#pragma unroll
                for (int nt = 0; nt < 8; nt++) {
                    asm volatile(
                        "mma.sync.aligned.m16n8k8.row.col.f32.tf32.tf32.f32 "
                        "{%0,%1,%2,%3},{%4,%5,%6,%7},{%8,%9},{%0,%1,%2,%3};"
                        : "+f"(acc[mt][nt][0]), "+f"(acc[mt][nt][1]),
                          "+f"(acc[mt][nt][2]), "+f"(acc[mt][nt][3])
                        : "r"(a[mt][0]), "r"(a[mt][1]), "r"(a[mt][2]), "r"(a[mt][3]),
                          "r"(b[nt][0]), "r"(b[nt][1]));
                }
        }
        __syncthreads();
        issue(it + 3);
    }

    // Epilogue: bias add + float2 stores.
#pragma unroll
    for (int mt = 0; mt < 4; mt++) {
        size_t r0 = (size_t)(bm + wm * 64 + mt * 16 + g);
#pragma unroll
        for (int nt = 0; nt < 8; nt++) {
            int col = bn + wn * 64 + nt * 8 + 2 * t;
            float b0v = bias[col], b1v = bias[col + 1];
            *(float2*)&Y[r0 * N_DIM + col] =
                make_float2(acc[mt][nt][0] + b0v, acc[mt][nt][1] + b1v);
            *(float2*)&Y[(r0 + 8) * N_DIM + col] =
                make_float2(acc[mt][nt][2] + b0v, acc[mt][nt][3] + b1v);
        }
    }
}

extern "C" void kernel_launch(void* const* d_in, const int* in_sizes, int n_in,
                              void* d_out, int out_size) {
    const float* x     = (const float*)d_in[0];
    const float* core0 = (const float*)d_in[1];
    const float* core1 = (const float*)d_in[2];
    const float* core2 = (const float*)d_in[3];
    const float* core3 = (const float*)d_in[4];
    const float* bias  = (const float*)d_in[5];
    float* y = (float*)d_out;

    cudaFuncSetAttribute(tt_gemm2, cudaFuncAttributeMaxDynamicSharedMemorySize, SMEM_SZ);

    x_round<<<4096, 256>>>(x);
    tt_stage1<<<256, 256>>>(core0, core1);
    tt_stage23<<<512, 256>>>(core2, core3);

    dim3 grid(N_DIM / 128, M_DIM / 128);   // 32 x 32
    tt_gemm2<<<grid, 128, SMEM_SZ>>>(bias, y);
}

// round 7
// speedup vs baseline: 2.1385x; 1.5776x over previous
#include <cuda_runtime.h>
#include <cuda_fp16.h>
#include <cstdint>

#define K_DIM 1024
#define N_DIM 4096
#define M_DIM 4096

// Scratch (allocation-free).
__device__ __half g_Wh[(size_t)N_DIM * K_DIM];      // TRANSPOSED: [n][k], fp16
__device__ __half g_Xh[(size_t)M_DIM * K_DIM];      // X, fp16

__device__ __forceinline__ uint32_t smem_u32(const void* p) {
    uint32_t a;
    asm("{ .reg .u64 t; cvta.to.shared.u64 t, %1; cvt.u32.u64 %0, t; }" : "=r"(a) : "l"(p));
    return a;
}

// ---------------- Fused TT-core staging: W from 4 cores in ONE kernel ----------------
// Block b = (n1,n2,n3). Thread owns (m1,m2,m3).
// a[r2] = sum_r1 c0[m1,n1,r1]*c1[r1,m2,n2,r2]; t[r3] = sum_r2 a[r2]*c2[r2,m3,n3,r3];
// Wh[n][k] = sum_r3 t[r3]*c3[r3,m4,n4].
__global__ __launch_bounds__(256) void tt_stageW(const float* __restrict__ core0,
                                                 const float* __restrict__ core1,
                                                 const float* __restrict__ core2,
                                                 const float* __restrict__ core3) {
    __shared__ float sC0[128];    // [m1][r1]           (n1 fixed)
    __shared__ float sC1[2048];   // [r1][m2][r2]       (n2 fixed)
    __shared__ float sC2[1024];   // [r2][m3][r3]       (n3 fixed)
    __shared__ float sC3[512];    // [r3][m4][n4]

    const int b = blockIdx.x;                         // 512 = (n1,n2,n3)
    const int n1 = b >> 6, n2 = (b >> 3) & 7, n3 = b & 7;
    const int tid = threadIdx.x;

    if (tid < 32) {   // sC0: c = m1*4 + r1q
        int m1 = tid >> 2, r1q = tid & 3;
        ((float4*)sC0)[tid] = *(const float4*)&core0[(m1 * 8 + n1) * 16 + r1q * 4];
    }
#pragma unroll
    for (int rd = 0; rd < 2; rd++) {   // sC1: 512 float4 chunks
        int c = rd * 256 + tid;
        int r1 = c >> 5, m2 = (c >> 2) & 7, r2q = c & 3;
        ((float4*)sC1)[c] = *(const float4*)&core1[r1 * 1024 + m2 * 128 + n2 * 16 + r2q * 4];
    }
    {   // sC2: c = r2*16 + m3*4 + r3q
        int r2 = tid >> 4, m3 = (tid >> 2) & 3, r3q = tid & 3;
        ((float4*)sC2)[tid] = *(const float4*)&core2[r2 * 512 + m3 * 128 + n3 * 16 + r3q * 4];
    }
    if (tid < 128) ((float4*)sC3)[tid] = ((const float4*)core3)[tid];
    __syncthreads();

    const int m1 = tid >> 5, m2 = (tid >> 2) & 7, m3 = tid & 3;
    float a[16], t[16];
#pragma unroll
    for (int r2 = 0; r2 < 16; r2++) a[r2] = 0.f;
#pragma unroll
    for (int r1 = 0; r1 < 16; r1++) {
        float c0v = sC0[m1 * 16 + r1];
#pragma unroll
        for (int r2 = 0; r2 < 16; r2++) a[r2] += c0v * sC1[r1 * 128 + m2 * 16 + r2];
    }
#pragma unroll
    for (int r3 = 0; r3 < 16; r3++) t[r3] = 0.f;
#pragma unroll
    for (int r2 = 0; r2 < 16; r2++) {
        float av = a[r2];
#pragma unroll
        for (int r3 = 0; r3 < 16; r3++) t[r3] += av * sC2[r2 * 64 + m3 * 16 + r3];
    }

    // k4 chunk = m1*32 + m2*4 + m3 == tid -> coalesced 8B stores per n4 row.
    const size_t nbase = (size_t)b * 8;
#pragma unroll
    for (int n4 = 0; n4 < 8; n4++) {
        float s[4];
#pragma unroll
        for (int m4 = 0; m4 < 4; m4++) {
            float acc = 0.f;
#pragma unroll
            for (int r3 = 0; r3 < 16; r3++) acc += t[r3] * sC3[r3 * 32 + m4 * 8 + n4];
            s[m4] = acc;
        }
        __half* dst = &g_Wh[(nbase + n4) * K_DIM + tid * 4];
        *(__half2*)dst       = __floats2half2_rn(s[0], s[1]);
        *(__half2*)(dst + 2) = __floats2half2_rn(s[2], s[3]);
    }
}

// Convert X to fp16 (8 floats -> 8 halves = 16B store per thread).
__global__ void x_half(const float* __restrict__ X) {
    int i = blockIdx.x * 256 + threadIdx.x;          // 524288
    float4 v0 = ((const float4*)X)[2 * i];
    float4 v1 = ((const float4*)X)[2 * i + 1];
    __half2 h[4];
    h[0] = __floats2half2_rn(v0.x, v0.y);
    h[1] = __floats2half2_rn(v0.z, v0.w);
    h[2] = __floats2half2_rn(v1.x, v1.y);
    h[3] = __floats2half2_rn(v1.z, v1.w);
    ((uint4*)g_Xh)[i] = *(uint4*)h;
}

// ---------------- fp16 mma.sync GEMM, cp.async 4-stage single-sync pipeline ----------------
// CTA 128x128, 128 threads (4 warps 2x2), warp tile 64x64, BK=32 (64B rows).
// Smem rows 64B = 4x16B units, swizzled: unit ^= (row>>1)&3. Conflict-free for
// fragment reads (banks 16(g&1)+4(u^(g>>1))+t all distinct) and cp.async stores.

#define BK 32
#define A_BYTES 8192                 // 128 rows x 64B
#define STAGE_BYTES 16384            // A 8KB + B 8KB
#define NSTAGE 4
#define SMEM_SZ (NSTAGE * STAGE_BYTES)
#define NITER (K_DIM / BK)

__device__ __forceinline__ void cp16(uint32_t dst, const void* src) {
    asm volatile("cp.async.cg.shared.global [%0], [%1], 16;" :: "r"(dst), "l"(src) : "memory");
}

__global__ __launch_bounds__(128, 2) void tt_gemm3(const float* __restrict__ bias,
                                                   float* __restrict__ Y) {
    extern __shared__ __align__(1024) char smem[];
    const uint32_t sb = smem_u32(smem);
    const int tid = threadIdx.x, lane = tid & 31, warp = tid >> 5;
    const int wm = warp >> 1, wn = warp & 1;
    const int g = lane >> 2, t = lane & 3;
    const int gp = (g >> 1) & 3;
    const int bm = blockIdx.y * 128, bn = blockIdx.x * 128;

    const __half* gA = g_Xh + (size_t)bm * K_DIM;
    const __half* gB = g_Wh + (size_t)bn * K_DIM;

    float acc[4][8][4];
#pragma unroll
    for (int a = 0; a < 4; a++)
#pragma unroll
        for (int b = 0; b < 8; b++)
#pragma unroll
            for (int c = 0; c < 4; c++) acc[a][b][c] = 0.f;

    // chunk c = i*128 + tid -> row m = c>>2, unit j = c&3.
    auto issue = [&](int it) {
        if (it < NITER) {
            const int s = it & 3;
            const uint32_t a0 = sb + s * STAGE_BYTES;
            const uint32_t b0 = a0 + A_BYTES;
            const int kt = it * BK;
#pragma unroll
            for (int i = 0; i < 4; i++) {
                int c = i * 128 + tid;
                int m = c >> 2, j = c & 3;
                uint32_t off = (uint32_t)(m * 64 + ((j ^ ((m >> 1) & 3)) << 4));
                cp16(a0 + off, gA + (size_t)m * K_DIM + kt + j * 8);
                cp16(b0 + off, gB + (size_t)m * K_DIM + kt + j * 8);
            }
        }
        asm volatile("cp.async.commit_group;" ::: "memory");
    };

    issue(0); issue(1); issue(2);

    int rowA[4], rowB[8];
#pragma unroll
    for (int mt = 0; mt < 4; mt++) rowA[mt] = (wm * 64 + mt * 16 + g) * 64;
#pragma unroll
    for (int nt = 0; nt < 8; nt++) rowB[nt] = (wn * 64 + nt * 8 + g) * 64;

    for (int it = 0; it < NITER; it++) {
        const int s = it & 3;
        asm volatile("cp.async.wait_group 2;" ::: "memory");
        __syncthreads();
        issue(it + 3);                               // stage (it+3)&3, read-done at it-1
        const uint32_t a0 = sb + s * STAGE_BYTES;
        const uint32_t b0 = a0 + A_BYTES;

#pragma unroll
        for (int kk = 0; kk < 2; kk++) {             // K sub-step of 16
            const uint32_t o0 = (uint32_t)((((2 * kk)     ^ gp) << 4) + 4 * t);
            const uint32_t o1 = (uint32_t)((((2 * kk + 1) ^ gp) << 4) + 4 * t);
            unsigned a[4][4], b[8][2];
#pragma unroll
            for (int mt = 0; mt < 4; mt++) {
                uint32_t r0 = a0 + rowA[mt];
                asm("ld.shared.b32 %0,[%1];" : "=r"(a[mt][0]) : "r"(r0 + o0));
                asm("ld.shared.b32 %0,[%1];" : "=r"(a[mt][1]) : "r"(r0 + 512 + o0));
                asm("ld.shared.b32 %0,[%1];" : "=r"(a[mt][2]) : "r"(r0 + o1));
                asm("ld.shared.b32 %0,[%1];" : "=r"(a[mt][3]) : "r"(r0 + 512 + o1));
            }
#pragma unroll
            for (int nt = 0; nt < 8; nt++) {
                uint32_t r0 = b0 + rowB[nt];
                asm("ld.shared.b32 %0,[%1];" : "=r"(b[nt][0]) : "r"(r0 + o0));
                asm("ld.shared.b32 %0,[%1];" : "=r"(b[nt][1]) : "r"(r0 + o1));
            }
#pragma unroll
            for (int mt = 0; mt < 4; mt++)
#pragma unroll
                for (int nt = 0; nt < 8; nt++) {
                    asm volatile(
                        "mma.sync.aligned.m16n8k16.row.col.f32.f16.f16.f32 "
                        "{%0,%1,%2,%3},{%4,%5,%6,%7},{%8,%9},{%0,%1,%2,%3};"
                        : "+f"(acc[mt][nt][0]), "+f"(acc[mt][nt][1]),
                          "+f"(acc[mt][nt][2]), "+f"(acc[mt][nt][3])
                        : "r"(a[mt][0]), "r"(a[mt][1]), "r"(a[mt][2]), "r"(a[mt][3]),
                          "r"(b[nt][0]), "r"(b[nt][1]));
                }
        }
    }

    // Epilogue: bias add + float2 stores.
#pragma unroll
    for (int mt = 0; mt < 4; mt++) {
        size_t r0 = (size_t)(bm + wm * 64 + mt * 16 + g);
#pragma unroll
        for (int nt = 0; nt < 8; nt++) {
            int col = bn + wn * 64 + nt * 8 + 2 * t;
            float b0v = bias[col], b1v = bias[col + 1];
            *(float2*)&Y[r0 * N_DIM + col] =
                make_float2(acc[mt][nt][0] + b0v, acc[mt][nt][1] + b1v);
            *(float2*)&Y[(r0 + 8) * N_DIM + col] =
                make_float2(acc[mt][nt][2] + b0v, acc[mt][nt][3] + b1v);
        }
    }
}

extern "C" void kernel_launch(void* const* d_in, const int* in_sizes, int n_in,
                              void* d_out, int out_size) {
    const float* x     = (const float*)d_in[0];
    const float* core0 = (const float*)d_in[1];
    const float* core1 = (const float*)d_in[2];
    const float* core2 = (const float*)d_in[3];
    const float* core3 = (const float*)d_in[4];
    const float* bias  = (const float*)d_in[5];
    float* y = (float*)d_out;

    cudaFuncSetAttribute(tt_gemm3, cudaFuncAttributeMaxDynamicSharedMemorySize, SMEM_SZ);

    x_half<<<2048, 256>>>(x);
    tt_stageW<<<512, 256>>>(core0, core1, core2, core3);

    dim3 grid(N_DIM / 128, M_DIM / 128);   // 32 x 32
    tt_gemm3<<<grid, 128, SMEM_SZ>>>(bias, y);
}

// round 9
// speedup vs baseline: 2.3709x; 1.1087x over previous
#include <cuda_runtime.h>
#include <cuda_fp16.h>
#include <cstdint>

#define K_DIM 1024
#define N_DIM 4096
#define M_DIM 4096

// Scratch (allocation-free).
__device__ __half g_Wh[(size_t)N_DIM * K_DIM];      // TRANSPOSED: [n][k], fp16
__device__ __half g_Xh[(size_t)M_DIM * K_DIM];      // X, fp16

__device__ __forceinline__ uint32_t smem_u32(const void* p) {
    uint32_t a;
    asm("{ .reg .u64 t; cvta.to.shared.u64 t, %1; cvt.u32.u64 %0, t; }" : "=r"(a) : "l"(p));
    return a;
}

// ---------------- Fused TT-core staging: W from 4 cores in ONE kernel ----------------
__global__ __launch_bounds__(256) void tt_stageW(const float* __restrict__ core0,
                                                 const float* __restrict__ core1,
                                                 const float* __restrict__ core2,
                                                 const float* __restrict__ core3) {
    __shared__ float sC0[128];    // [m1][r1]           (n1 fixed)
    __shared__ float sC1[2048];   // [r1][m2][r2]       (n2 fixed)
    __shared__ float sC2[1024];   // [r2][m3][r3]       (n3 fixed)
    __shared__ float sC3[512];    // [r3][m4][n4]

    const int b = blockIdx.x;                         // 512 = (n1,n2,n3)
    const int n1 = b >> 6, n2 = (b >> 3) & 7, n3 = b & 7;
    const int tid = threadIdx.x;

    if (tid < 32) {
        int m1 = tid >> 2, r1q = tid & 3;
        ((float4*)sC0)[tid] = *(const float4*)&core0[(m1 * 8 + n1) * 16 + r1q * 4];
    }
#pragma unroll
    for (int rd = 0; rd < 2; rd++) {
        int c = rd * 256 + tid;
        int r1 = c >> 5, m2 = (c >> 2) & 7, r2q = c & 3;
        ((float4*)sC1)[c] = *(const float4*)&core1[r1 * 1024 + m2 * 128 + n2 * 16 + r2q * 4];
    }
    {
        int r2 = tid >> 4, m3 = (tid >> 2) & 3, r3q = tid & 3;
        ((float4*)sC2)[tid] = *(const float4*)&core2[r2 * 512 + m3 * 128 + n3 * 16 + r3q * 4];
    }
    if (tid < 128) ((float4*)sC3)[tid] = ((const float4*)core3)[tid];
    __syncthreads();

    const int m1 = tid >> 5, m2 = (tid >> 2) & 7, m3 = tid & 3;
    float a[16], t[16];
#pragma unroll
    for (int r2 = 0; r2 < 16; r2++) a[r2] = 0.f;
#pragma unroll
    for (int r1 = 0; r1 < 16; r1++) {
        float c0v = sC0[m1 * 16 + r1];
#pragma unroll
        for (int r2 = 0; r2 < 16; r2++) a[r2] += c0v * sC1[r1 * 128 + m2 * 16 + r2];
    }
#pragma unroll
    for (int r3 = 0; r3 < 16; r3++) t[r3] = 0.f;
#pragma unroll
    for (int r2 = 0; r2 < 16; r2++) {
        float av = a[r2];
#pragma unroll
        for (int r3 = 0; r3 < 16; r3++) t[r3] += av * sC2[r2 * 64 + m3 * 16 + r3];
    }

    const size_t nbase = (size_t)b * 8;
#pragma unroll
    for (int n4 = 0; n4 < 8; n4++) {
        float s[4];
#pragma unroll
        for (int m4 = 0; m4 < 4; m4++) {
            float acc = 0.f;
#pragma unroll
            for (int r3 = 0; r3 < 16; r3++) acc += t[r3] * sC3[r3 * 32 + m4 * 8 + n4];
            s[m4] = acc;
        }
        __half* dst = &g_Wh[(nbase + n4) * K_DIM + tid * 4];
        *(__half2*)dst       = __floats2half2_rn(s[0], s[1]);
        *(__half2*)(dst + 2) = __floats2half2_rn(s[2], s[3]);
    }
}

// Convert X to fp16.
__global__ void x_half(const float* __restrict__ X) {
    int i = blockIdx.x * 256 + threadIdx.x;          // 524288
    float4 v0 = ((const float4*)X)[2 * i];
    float4 v1 = ((const float4*)X)[2 * i + 1];
    __half2 h[4];
    h[0] = __floats2half2_rn(v0.x, v0.y);
    h[1] = __floats2half2_rn(v0.z, v0.w);
    h[2] = __floats2half2_rn(v1.x, v1.y);
    h[3] = __floats2half2_rn(v1.z, v1.w);
    ((uint4*)g_Xh)[i] = *(uint4*)h;
}

// ---------------- fp16 mma.sync GEMM: ldmatrix + BK=64, 3-stage cp.async ----------------
// CTA 128x128, 128 threads (4 warps 2x2), warp tile 64x64.
// Smem rows 128B = 8x16B units, SW128 swizzle: unit ^= row&7.

#define BK 64
#define A_BYTES 16384                // 128 rows x 128B
#define STAGE_BYTES 32768            // A 16KB + B 16KB
#define NSTAGE 3
#define SMEM_SZ (NSTAGE * STAGE_BYTES)
#define NITER (K_DIM / BK)

__device__ __forceinline__ void cp16(uint32_t dst, const void* src) {
    asm volatile("cp.async.cg.shared.global [%0], [%1], 16;" :: "r"(dst), "l"(src) : "memory");
}
#define LDSM4(r0, r1, r2, r3, addr)                                          \
    asm volatile("ldmatrix.sync.aligned.m8n8.x4.shared.b16 {%0,%1,%2,%3},[%4];" \
        : "=r"(r0), "=r"(r1), "=r"(r2), "=r"(r3) : "r"(addr))

__global__ __launch_bounds__(128, 2) void tt_gemm4(const float* __restrict__ bias,
                                                   float* __restrict__ Y) {
    extern __shared__ __align__(1024) char smem[];
    const uint32_t sb = smem_u32(smem);
    const int tid = threadIdx.x, lane = tid & 31, warp = tid >> 5;
    const int wm = warp >> 1, wn = warp & 1;
    const int g = lane >> 2, t = lane & 3;
    const int bm = blockIdx.y * 128, bn = blockIdx.x * 128;

    const __half* gA = g_Xh + (size_t)bm * K_DIM;
    const __half* gB = g_Wh + (size_t)bn * K_DIM;

    float acc[4][8][4];
#pragma unroll
    for (int a = 0; a < 4; a++)
#pragma unroll
        for (int b = 0; b < 8; b++)
#pragma unroll
            for (int c = 0; c < 4; c++) acc[a][b][c] = 0.f;

    // cp.async: chunk c = i*128 + tid -> row m = c>>3, unit j = c&7 (1024 chunks/operand).
    auto issue = [&](int it) {
        if (it < NITER) {
            const int s = it % NSTAGE;
            const uint32_t a0 = sb + s * STAGE_BYTES;
            const uint32_t b0 = a0 + A_BYTES;
            const int kt = it * BK;
#pragma unroll
            for (int i = 0; i < 8; i++) {
                int c = i * 128 + tid;
                int m = c >> 3, j = c & 7;
                uint32_t off = (uint32_t)(m * 128 + ((j ^ (m & 7)) << 4));
                cp16(a0 + off, gA + (size_t)m * K_DIM + kt + j * 8);
                cp16(b0 + off, gB + (size_t)m * K_DIM + kt + j * 8);
            }
        }
        asm volatile("cp.async.commit_group;" ::: "memory");
    };

    issue(0); issue(1);

    // ldmatrix lane geometry. r7 = lane&7 for both operands (row offsets are mult. of 8).
    const int r7  = lane & 7;
    const int uAp = lane >> 4;          // A: lanes 16-31 take the hi 16B unit
    const int uBp = (lane >> 3) & 1;    // B: phase pairs alternate units
    uint32_t baseA[4], baseB[4];
#pragma unroll
    for (int mt = 0; mt < 4; mt++) {
        int rowA = wm * 64 + mt * 16 + (lane & 15);
        baseA[mt] = rowA * 128;         // + stage base at use
    }
#pragma unroll
    for (int p = 0; p < 4; p++) {
        int rowB = wn * 64 + p * 16 + ((lane >> 4) << 3) + (lane & 7);
        baseB[p] = rowB * 128;
    }

    for (int it = 0; it < NITER; it++) {
        const int s = it % NSTAGE;
        asm volatile("cp.async.wait_group 1;" ::: "memory");
        __syncthreads();
        issue(it + 2);                   // stage (it+2)%3: last read at iter it-1
        const uint32_t a0 = sb + s * STAGE_BYTES;
        const uint32_t b0 = a0 + A_BYTES;

#pragma unroll
        for (int kk = 0; kk < 4; kk++) { // K sub-step of 16
            const uint32_t oA = (uint32_t)(((2 * kk + uAp) ^ r7) << 4);
            const uint32_t oB = (uint32_t)(((2 * kk + uBp) ^ r7) << 4);
            unsigned a[4][4], b[8][2];
#pragma unroll
            for (int mt = 0; mt < 4; mt++)
                LDSM4(a[mt][0], a[mt][1], a[mt][2], a[mt][3], a0 + baseA[mt] + oA);
#pragma unroll
            for (int p = 0; p < 4; p++)
                LDSM4(b[2 * p][0], b[2 * p][1], b[2 * p + 1][0], b[2 * p + 1][1],
                      b0 + baseB[p] + oB);
#pragma unroll
            for (int mt = 0; mt < 4; mt++)
#pragma unroll
                for (int nt = 0; nt < 8; nt++) {
                    asm volatile(
                        "mma.sync.aligned.m16n8k16.row.col.f32.f16.f16.f32 "
                        "{%0,%1,%2,%3},{%4,%5,%6,%7},{%8,%9},{%0,%1,%2,%3};"
                        : "+f"(acc[mt][nt][0]), "+f"(acc[mt][nt][1]),
                          "+f"(acc[mt][nt][2]), "+f"(acc[mt][nt][3])
                        : "r"(a[mt][0]), "r"(a[mt][1]), "r"(a[mt][2]), "r"(a[mt][3]),
                          "r"(b[nt][0]), "r"(b[nt][1]));
                }
        }
    }

    // Epilogue: bias add + float2 stores.
#pragma unroll
    for (int mt = 0; mt < 4; mt++) {
        size_t r0 = (size_t)(bm + wm * 64 + mt * 16 + g);
#pragma unroll
        for (int nt = 0; nt < 8; nt++) {
            int col = bn + wn * 64 + nt * 8 + 2 * t;
            float b0v = bias[col], b1v = bias[col + 1];
            *(float2*)&Y[r0 * N_DIM + col] =
                make_float2(acc[mt][nt][0] + b0v, acc[mt][nt][1] + b1v);
            *(float2*)&Y[(r0 + 8) * N_DIM + col] =
                make_float2(acc[mt][nt][2] + b0v, acc[mt][nt][3] + b1v);
        }
    }
}

extern "C" void kernel_launch(void* const* d_in, const int* in_sizes, int n_in,
                              void* d_out, int out_size) {
    const float* x     = (const float*)d_in[0];
    const float* core0 = (const float*)d_in[1];
    const float* core1 = (const float*)d_in[2];
    const float* core2 = (const float*)d_in[3];
    const float* core3 = (const float*)d_in[4];
    const float* bias  = (const float*)d_in[5];
    float* y = (float*)d_out;

    cudaFuncSetAttribute(tt_gemm4, cudaFuncAttributeMaxDynamicSharedMemorySize, SMEM_SZ);

    x_half<<<2048, 256>>>(x);
    tt_stageW<<<512, 256>>>(core0, core1, core2, core3);

    dim3 grid(N_DIM / 128, M_DIM / 128);   // 32 x 32
    tt_gemm4<<<grid, 128, SMEM_SZ>>>(bias, y);
}